// round 10
// baseline (speedup 1.0000x reference)
#include <cuda_runtime.h>
#include <cuda_bf16.h>
#include <stdint.h>

#define TM 128
#define THREADS 512
#define APADF 40   // A row stride in floats (fp32 staging)
#define BPAD 40    // B row stride in bf16
#define HP 264
#define ASTG 20480 // 128*APADF*4
#define BSTG 20480 // 256*BPAD*2

// SMEM layout (bytes)
#define SM_A 0
#define SM_B 61440
#define SM_H 122880
#define SM_LG 190464
#define SM_BIAS 199168
#define SM_BPRED 200192
#define SM_EM 201216
#define SM_SPAIR 202752
#define SM_SLABEL 203264
#define SM_PSUM 203776
#define SM_PCNT 203840
#define SM_CNT 203904
#define SM_OFFP 203968
#define SM_CUR 204032
#define SM_BUCKET 204096
#define SMEM_TOTAL 204608

// device scratch
__device__ __align__(16) __nv_bfloat16 g_Wt[256 * 512];   // [n][k] decoder weights, bf16
__device__ __align__(16) __nv_bfloat16 g_Wp2[256 * 256];  // [p*16+c][k] head weights, bf16
__device__ float g_sums[16];
__device__ float g_cnts[16];
__device__ int g_done;

__global__ void prep_kernel(const float* __restrict__ W1, const float* __restrict__ W2,
                            const float* __restrict__ Wp) {
  int i = blockIdx.x * blockDim.x + threadIdx.x;
  if (i < 256 * 512) {
    int n = i >> 9, k = i & 511;
    float v = (k < 256) ? W1[k * 256 + n] : W2[(k - 256) * 256 + n];
    g_Wt[n * 512 + k] = __float2bfloat16(v);
  }
  if (i < 256 * 256) {
    int col = i >> 8, k = i & 255;
    int p = col >> 4, c = col & 15;
    g_Wp2[col * 256 + k] = __float2bfloat16(Wp[p * 4096 + k * 16 + c]);
  }
  if (i < 16) { g_sums[i] = 0.f; g_cnts[i] = 0.f; }
  if (i == 0) g_done = 0;
}

__device__ __forceinline__ void mma16816(float* c, uint32_t a0, uint32_t a1, uint32_t a2,
                                         uint32_t a3, uint32_t b0, uint32_t b1) {
  asm volatile(
      "mma.sync.aligned.m16n8k16.row.col.f32.bf16.bf16.f32 "
      "{%0,%1,%2,%3}, {%4,%5,%6,%7}, {%8,%9}, {%0,%1,%2,%3};\n"
      : "+f"(c[0]), "+f"(c[1]), "+f"(c[2]), "+f"(c[3])
      : "r"(a0), "r"(a1), "r"(a2), "r"(a3), "r"(b0), "r"(b1));
}

__device__ __forceinline__ uint32_t s2u(const void* p) {
  uint32_t a;
  asm("{ .reg .u64 t; cvta.to.shared.u64 t, %1; cvt.u32.u64 %0, t; }" : "=r"(a) : "l"(p));
  return a;
}
__device__ __forceinline__ void cp16(uint32_t dst, const void* src) {
  asm volatile("cp.async.cg.shared.global [%0], [%1], 16;" ::"r"(dst), "l"(src) : "memory");
}
__device__ __forceinline__ void cp_commit() {
  asm volatile("cp.async.commit_group;" ::: "memory");
}
__device__ __forceinline__ void cp_wait1() {
  asm volatile("cp.async.wait_group 1;" ::: "memory");
}

__device__ __forceinline__ uint32_t cvt2(float2 v) {
  __nv_bfloat162 p = __floats2bfloat162_rn(v.x, v.y);
  return *(uint32_t*)&p;
}

// issue cp.async for chunk c (k in [c*32, c*32+32)) into stage buffer s
__device__ __forceinline__ void issue_chunk(uint32_t su, const float* hs, const float* hd,
                                            long e0, int c, int s, int t, int E) {
  // A: thread t -> row t>>2, 32B segment (t&3) of 128B row-chunk (fp32)
  {
    int row = t >> 2, seg = t & 3;
    long e = e0 + row; if (e >= E) e = E - 1;
    int kg = c * 32 + seg * 8;
    const float* p = (kg < 256) ? hs + e * 256 + kg : hd + e * 256 + (kg - 256);
    uint32_t d = su + SM_A + s * ASTG + row * (APADF * 4) + seg * 32;
    cp16(d, p);
    cp16(d + 16, p + 4);
  }
  // B: thread t -> row t>>1, 32B half (t&1) of 64B row-chunk (bf16)
  {
    int row = t >> 1, half = t & 1;
    const __nv_bfloat16* p = g_Wt + row * 512 + c * 32 + half * 16;
    uint32_t d = su + SM_B + s * BSTG + row * (BPAD * 2) + half * 32;
    cp16(d, p);
    cp16(d + 16, p + 8);
  }
}

__global__ __launch_bounds__(THREADS, 1)
void main_kernel(const float* __restrict__ h_src, const float* __restrict__ h_dst,
                 const float* __restrict__ b_dec, const float* __restrict__ b_pred,
                 const int* __restrict__ st, const int* __restrict__ dt,
                 const int* __restrict__ etc, const int* __restrict__ emap,
                 float* __restrict__ out, int E) {
  extern __shared__ __align__(16) char smem[];
  const int tid = threadIdx.x;
  const int warp = tid >> 5, lane = tid & 31;
  const int wm = warp & 3, wn = warp >> 2;
  const long e0 = (long)blockIdx.x * TM;
  const uint32_t su = s2u(smem);
  const int kq = (lane & 3) * 2;
  const int rb = lane >> 2;

  float* bias = (float*)(smem + SM_BIAS);
  float* bpred = (float*)(smem + SM_BPRED);
  int* em = (int*)(smem + SM_EM);
  int* spair = (int*)(smem + SM_SPAIR);
  int* slabel = (int*)(smem + SM_SLABEL);
  float* psum = (float*)(smem + SM_PSUM);
  int* pcnt = (int*)(smem + SM_PCNT);
  int* cnt = (int*)(smem + SM_CNT);
  int* offp = (int*)(smem + SM_OFFP);
  int* curp = (int*)(smem + SM_CUR);
  int* bucket = (int*)(smem + SM_BUCKET);
  float* Lg = (float*)(smem + SM_LG);

  // pipeline prologue: chunks 0,1 in flight
  issue_chunk(su, h_src, h_dst, e0, 0, 0, tid, E);
  cp_commit();
  issue_chunk(su, h_src, h_dst, e0, 1, 1, tid, E);
  cp_commit();

  for (int i = tid; i < 256; i += THREADS) { bias[i] = b_dec[i]; bpred[i] = b_pred[i]; }
  for (int i = tid; i < 384; i += THREADS) em[i] = emap[i];
  if (tid < 16) { psum[tid] = 0.f; pcnt[tid] = 0; cnt[tid] = 0; }
  __syncthreads();
  if (tid < 128) {
    long e = e0 + tid; if (e >= E) e = E - 1;
    int p = st[e] * 4 + dt[e];
    spair[tid] = p;
    slabel[tid] = em[p * 24 + etc[e]];
    atomicAdd(&cnt[p], 1);
  }
  __syncthreads();
  if (tid == 0) {
    int a = 0;
#pragma unroll
    for (int p = 0; p < 16; ++p) { offp[p] = a; curp[p] = a; a += cnt[p]; }
  }
  __syncthreads();
  if (tid < 128) {
    int pos = atomicAdd(&curp[spair[tid]], 1);
    bucket[pos] = tid;
  }

  // ---- GEMM1: h = relu([h_src|h_dst] @ Wt^T + b), KC=32, 3-stage cp.async ----
  float acc[2][8][4];
#pragma unroll
  for (int a = 0; a < 2; a++)
#pragma unroll
    for (int b = 0; b < 8; b++)
#pragma unroll
      for (int c = 0; c < 4; c++) acc[a][b][c] = 0.f;

  int sidx = 0;  // stage of current chunk
  for (int it = 0; it < 16; ++it) {
    cp_wait1();      // chunk `it` has landed (only it+1 may be pending)
    __syncthreads(); // all warps done with the buffer we are about to overwrite
    if (it + 2 < 16) {
      int s2 = sidx + 2; if (s2 >= 3) s2 -= 3;
      issue_chunk(su, h_src, h_dst, e0, it + 2, s2, tid, E);
    }
    cp_commit();  // always commit to keep group accounting uniform
    const float* Af = (const float*)(smem + SM_A + sidx * ASTG);
    const __nv_bfloat16* Bb = (const __nv_bfloat16*)(smem + SM_B + sidx * BSTG);
#pragma unroll
    for (int ks = 0; ks < 2; ++ks) {
      const int kk = ks * 16 + kq;
      uint32_t af[2][4];
#pragma unroll
      for (int mi = 0; mi < 2; ++mi) {
        int r = wm * 32 + mi * 16 + rb;
        af[mi][0] = cvt2(*(const float2*)(Af + r * APADF + kk));
        af[mi][1] = cvt2(*(const float2*)(Af + (r + 8) * APADF + kk));
        af[mi][2] = cvt2(*(const float2*)(Af + r * APADF + kk + 8));
        af[mi][3] = cvt2(*(const float2*)(Af + (r + 8) * APADF + kk + 8));
      }
#pragma unroll
      for (int ni = 0; ni < 8; ++ni) {
        int n = wn * 64 + ni * 8 + rb;
        uint32_t b0 = *(const uint32_t*)(Bb + n * BPAD + kk);
        uint32_t b1 = *(const uint32_t*)(Bb + n * BPAD + kk + 8);
        mma16816(acc[0][ni], af[0][0], af[0][1], af[0][2], af[0][3], b0, b1);
        mma16816(acc[1][ni], af[1][0], af[1][1], af[1][2], af[1][3], b0, b1);
      }
    }
    if (++sidx == 3) sidx = 0;
  }
  __syncthreads();

  // epilogue: bias + relu -> h (bf16 in smem)
  char* Hb = smem + SM_H;
#pragma unroll
  for (int mi = 0; mi < 2; ++mi) {
    int r = wm * 32 + mi * 16 + rb;
#pragma unroll
    for (int ni = 0; ni < 8; ++ni) {
      int n0 = wn * 64 + ni * 8 + (lane & 3) * 2;
      float bb0 = bias[n0], bb1 = bias[n0 + 1];
      __nv_bfloat162 q0 = __floats2bfloat162_rn(fmaxf(acc[mi][ni][0] + bb0, 0.f),
                                                fmaxf(acc[mi][ni][1] + bb1, 0.f));
      __nv_bfloat162 q1 = __floats2bfloat162_rn(fmaxf(acc[mi][ni][2] + bb0, 0.f),
                                                fmaxf(acc[mi][ni][3] + bb1, 0.f));
      *(uint32_t*)(Hb + (r * HP + n0) * 2) = *(uint32_t*)&q0;
      *(uint32_t*)(Hb + ((r + 8) * HP + n0) * 2) = *(uint32_t*)&q1;
    }
  }
  __syncthreads();

  // ---- GEMM2 (bucketed): warp w handles pair w; only the selected head ----
  {
    const int p = warp;
    const int m = cnt[p];
    const int off = offp[p];
    const __nv_bfloat16* Hh = (const __nv_bfloat16*)(smem + SM_H);
    const __nv_bfloat16* Wb = g_Wp2 + (p * 16) * 256;  // 16 cols x 256 k, L2-hot
    for (int t = 0; t * 16 < m; ++t) {
      int i0 = t * 16 + rb, i1 = i0 + 8;
      int r0 = (i0 < m) ? bucket[off + i0] : bucket[off];
      int r1 = (i1 < m) ? bucket[off + i1] : bucket[off];
      float a0[4] = {0.f, 0.f, 0.f, 0.f};
      float a1[4] = {0.f, 0.f, 0.f, 0.f};
#pragma unroll 4
      for (int ks = 0; ks < 16; ++ks) {
        int kk = ks * 16 + kq;
        uint32_t f0 = *(const uint32_t*)(Hh + r0 * HP + kk);
        uint32_t f1 = *(const uint32_t*)(Hh + r1 * HP + kk);
        uint32_t f2 = *(const uint32_t*)(Hh + r0 * HP + kk + 8);
        uint32_t f3 = *(const uint32_t*)(Hh + r1 * HP + kk + 8);
        uint32_t b0 = *(const uint32_t*)(Wb + rb * 256 + kk);
        uint32_t b1 = *(const uint32_t*)(Wb + rb * 256 + kk + 8);
        uint32_t b2 = *(const uint32_t*)(Wb + (8 + rb) * 256 + kk);
        uint32_t b3 = *(const uint32_t*)(Wb + (8 + rb) * 256 + kk + 8);
        mma16816(a0, f0, f1, f2, f3, b0, b1);
        mma16816(a1, f0, f1, f2, f3, b2, b3);
      }
      int c0 = (lane & 3) * 2;
      if (i0 < m) {
        Lg[r0 * 17 + c0] = a0[0];
        Lg[r0 * 17 + c0 + 1] = a0[1];
        Lg[r0 * 17 + 8 + c0] = a1[0];
        Lg[r0 * 17 + 8 + c0 + 1] = a1[1];
      }
      if (i1 < m) {
        Lg[r1 * 17 + c0] = a0[2];
        Lg[r1 * 17 + c0 + 1] = a0[3];
        Lg[r1 * 17 + 8 + c0] = a1[2];
        Lg[r1 * 17 + 8 + c0 + 1] = a1[3];
      }
    }
  }
  __syncthreads();

  // per-edge softmax NLL + per-pair partials
  if (tid < 128) {
    long e = e0 + tid;
    if (e < E) {
      const float* L = Lg + tid * 17;
      const float* bp = bpred + spair[tid] * 16;
      float mx = -1e30f;
      float Lb[16];
#pragma unroll
      for (int c = 0; c < 16; ++c) { Lb[c] = L[c] + bp[c]; mx = fmaxf(mx, Lb[c]); }
      float s = 0.f;
#pragma unroll
      for (int c = 0; c < 16; ++c) s += __expf(Lb[c] - mx);
      float l = __logf(s) + mx - Lb[slabel[tid]];
      atomicAdd(&psum[spair[tid]], l);
      atomicAdd(&pcnt[spair[tid]], 1);
    }
  }
  __syncthreads();
  if (tid < 16 && pcnt[tid] > 0) {
    atomicAdd(&g_sums[tid], psum[tid]);
    atomicAdd(&g_cnts[tid], (float)pcnt[tid]);
  }
  __threadfence();
  __syncthreads();
  if (tid == 0) {
    int prev = atomicAdd(&g_done, 1);
    if (prev == (int)gridDim.x - 1) {
      __threadfence();
      float ls = 0.f, np = 0.f;
#pragma unroll
      for (int p = 0; p < 16; ++p) {
        float c = g_cnts[p];
        if (c > 0.f) { ls += g_sums[p] / c; np += 1.f; }
      }
      out[0] = ls / np;
    }
  }
}

extern "C" void kernel_launch(void* const* d_in, const int* in_sizes, int n_in,
                              void* d_out, int out_size) {
  const float* h_src = (const float*)d_in[0];
  const float* h_dst = (const float*)d_in[1];
  const float* W1 = (const float*)d_in[2];
  const float* W2 = (const float*)d_in[3];
  const float* b_dec = (const float*)d_in[4];
  const float* W_pred = (const float*)d_in[5];
  const float* b_pred = (const float*)d_in[6];
  const int* st = (const int*)d_in[7];
  const int* dt = (const int*)d_in[8];
  const int* etc = (const int*)d_in[9];
  const int* em = (const int*)d_in[10];
  int E = in_sizes[7];

  cudaFuncSetAttribute(main_kernel, cudaFuncAttributeMaxDynamicSharedMemorySize, SMEM_TOTAL);
  prep_kernel<<<512, 256>>>(W1, W2, W_pred);
  int grid = (E + TM - 1) / TM;
  main_kernel<<<grid, THREADS, SMEM_TOTAL>>>(h_src, h_dst, b_dec, b_pred, st, dt, etc, em,
                                             (float*)d_out, E);
}